// round 1
// baseline (speedup 1.0000x reference)
#include <cuda_runtime.h>
#include <math.h>

// Problem constants
#define B   16
#define IC  64
#define OC  128
#define H   224
#define W   224
#define KS  3

// Tile config
#define TROWS 2      // output rows per CTA
#define TCOLS 16     // output cols per CTA
#define ICC   8      // input-channel chunk
#define XROWS (TROWS + 2)   // 4 rows incl. halo
#define XCOLS (TCOLS + 2)   // 18 cols incl. halo
#define XPITCH 20           // padded to 80B for float4-aligned rows

// Pre-transposed weights: wt[(ic*9 + k)*128 + oc]
__device__ float g_wt[IC * 9 * OC];

__global__ void transpose_weights(const float* __restrict__ Wg) {
    int idx = blockIdx.x * 256 + threadIdx.x;
    if (idx < OC * IC * 9) {
        int k  = idx % 9;
        int ic = (idx / 9) % IC;
        int oc = idx / (IC * 9);
        g_wt[(ic * 9 + k) * OC + oc] = Wg[idx];
    }
}

__global__ __launch_bounds__(256)
void conv_min_kernel(const float* __restrict__ x,
                     const float* __restrict__ bias,
                     float* __restrict__ out) {
    __shared__ __align__(16) float xs[ICC * XROWS * XPITCH];   // 2.56 KB
    __shared__ __align__(16) float ws[ICC * 9 * OC];           // 36 KB
    __shared__ float red[8][TCOLS];                            // per-warp partial mins

    const int tid = threadIdx.x;
    const int oc  = tid & 127;        // 0..127
    const int r   = tid >> 7;         // 0..1 (output row within tile)

    const int w0 = blockIdx.x * TCOLS;
    const int h0 = blockIdx.y * TROWS;
    const int b  = blockIdx.z;

    float acc[TCOLS];
    const float bv = bias[oc];
#pragma unroll
    for (int c = 0; c < TCOLS; ++c) acc[c] = bv;

    const float* xb = x + (size_t)b * IC * H * W;

    for (int ic0 = 0; ic0 < IC; ic0 += ICC) {
        // ---- stage input tile (with zero halo) ----
        for (int idx = tid; idx < ICC * XROWS * XCOLS; idx += 256) {
            int col  = idx % XCOLS;
            int rowc = idx / XCOLS;
            int row  = rowc & 3;
            int icc  = rowc >> 2;
            int gh = h0 + row - 1;
            int gw = w0 + col - 1;
            float v = 0.0f;
            if (gh >= 0 && gh < H && gw >= 0 && gw < W)
                v = xb[((size_t)(ic0 + icc) * H + gh) * W + gw];
            xs[(icc * XROWS + row) * XPITCH + col] = v;
        }
        // ---- stage weight chunk: straight float4 copy (layout matches) ----
        {
            const float4* src = (const float4*)(g_wt + ic0 * 9 * OC);
            float4* dst = (float4*)ws;
            for (int i = tid; i < (ICC * 9 * OC) / 4; i += 256)
                dst[i] = src[i];
        }
        __syncthreads();

        // ---- compute ----
        for (int icc = 0; icc < ICC; ++icc) {
            float wv[9];
#pragma unroll
            for (int k = 0; k < 9; ++k)
                wv[k] = ws[(icc * 9 + k) * OC + oc];   // conflict-free: lane==oc contiguous
#pragma unroll
            for (int kh = 0; kh < 3; ++kh) {
                const float4* rowp =
                    (const float4*)&xs[(icc * XROWS + r + kh) * XPITCH];
                float4 v0 = rowp[0], v1 = rowp[1], v2 = rowp[2], v3 = rowp[3], v4 = rowp[4];
                float xa[20] = {v0.x, v0.y, v0.z, v0.w,
                                v1.x, v1.y, v1.z, v1.w,
                                v2.x, v2.y, v2.z, v2.w,
                                v3.x, v3.y, v3.z, v3.w,
                                v4.x, v4.y, v4.z, v4.w};
#pragma unroll
                for (int kw = 0; kw < 3; ++kw) {
                    const float wk = wv[kh * 3 + kw];
#pragma unroll
                    for (int c = 0; c < TCOLS; ++c)
                        acc[c] = fmaf(xa[kw + c], wk, acc[c]);
                }
            }
        }
        __syncthreads();
    }

    // ---- min over OC: butterfly within warp (32 distinct OCs, same pixels) ----
#pragma unroll
    for (int c = 0; c < TCOLS; ++c) {
        float v = acc[c];
#pragma unroll
        for (int off = 16; off > 0; off >>= 1)
            v = fminf(v, __shfl_xor_sync(0xffffffffu, v, off));
        acc[c] = v;   // every lane now holds warp min for column c
    }
    const int warp = tid >> 5;
    if ((tid & 31) == 0) {
#pragma unroll
        for (int c = 0; c < TCOLS; ++c) red[warp][c] = acc[c];
    }
    __syncthreads();

    // ---- cross-warp min (4 warps per output row), tanh(tanh(.)), store ----
    if (tid < 32) {
        int r2 = tid >> 4;          // output row 0/1
        int c  = tid & 15;          // column
        float m = red[r2 * 4 + 0][c];
        m = fminf(m, red[r2 * 4 + 1][c]);
        m = fminf(m, red[r2 * 4 + 2][c]);
        m = fminf(m, red[r2 * 4 + 3][c]);
        float y = tanhf(tanhf(m));  // monotone: min commutes with tanh∘tanh
        out[((size_t)b * H + (h0 + r2)) * W + (w0 + c)] = y;
    }
}

extern "C" void kernel_launch(void* const* d_in, const int* in_sizes, int n_in,
                              void* d_out, int out_size) {
    const float* x    = (const float*)d_in[0];
    const float* wgt  = (const float*)d_in[1];
    const float* bias = (const float*)d_in[2];
    float* out = (float*)d_out;

    transpose_weights<<<(OC * IC * 9 + 255) / 256, 256>>>(wgt);

    dim3 grid(W / TCOLS, H / TROWS, B);   // 14 x 112 x 16
    conv_min_kernel<<<grid, 256>>>(x, bias, out);
}

// round 3
// speedup vs baseline: 5.7249x; 5.7249x over previous
#include <cuda_runtime.h>
#include <cuda_fp8.h>
#include <cstdint>
#include <math.h>

#define Bn   16
#define ICn  64
#define OCn  128
#define Hn   224
#define Wn   224
#define HWn  (Hn * Wn)
#define NTILES (HWn / 128)   // 392
#define NTAPS 9

// fp8 scratch (module globals: allowed, not runtime allocation)
__device__ uint8_t g_x8[(size_t)Bn * HWn * ICn];        // [b][hw][ic]  51.4 MB
__device__ uint8_t g_w8[NTAPS * 4 * OCn * 16];          // [tap][chunk][oc][16]

__device__ __forceinline__ uint32_t smem_u32(const void* p) {
    uint32_t a;
    asm("{ .reg .u64 t; cvta.to.shared.u64 t, %1; cvt.u32.u64 %0, t; }"
        : "=r"(a) : "l"(p));
    return a;
}

// ---------------- prep kernels ----------------
__global__ void prep_w(const float* __restrict__ Wg) {
    int idx = blockIdx.x * 256 + threadIdx.x;
    if (idx < OCn * ICn * NTAPS) {
        int tap = idx % NTAPS;
        int ic  = (idx / NTAPS) % ICn;
        int oc  = idx / (NTAPS * ICn);
        uint8_t v = (uint8_t)__nv_cvt_float_to_fp8(Wg[idx], __NV_SATFINITE, __NV_E4M3);
        g_w8[((tap * 4 + (ic >> 4)) * OCn + oc) * 16 + (ic & 15)] = v;
    }
}

// Transpose+convert x: [ic][hw] fp32 -> [hw][ic] fp8 (per batch image)
__global__ __launch_bounds__(256) void prep_x(const float* __restrict__ x) {
    __shared__ uint8_t s[128 * 65];
    const int tile = blockIdx.x, b = blockIdx.y;
    const int hw0 = tile * 128;
    const int t = threadIdx.x;
    const int ic = t >> 2, q = t & 3;

    const float4* src =
        (const float4*)(x + (size_t)b * ICn * HWn + (size_t)ic * HWn + hw0 + q * 32);
#pragma unroll
    for (int j = 0; j < 8; ++j) {
        float4 v = src[j];
        int pix = q * 32 + j * 4;
        s[(pix + 0) * 65 + ic] = (uint8_t)__nv_cvt_float_to_fp8(v.x, __NV_SATFINITE, __NV_E4M3);
        s[(pix + 1) * 65 + ic] = (uint8_t)__nv_cvt_float_to_fp8(v.y, __NV_SATFINITE, __NV_E4M3);
        s[(pix + 2) * 65 + ic] = (uint8_t)__nv_cvt_float_to_fp8(v.z, __NV_SATFINITE, __NV_E4M3);
        s[(pix + 3) * 65 + ic] = (uint8_t)__nv_cvt_float_to_fp8(v.w, __NV_SATFINITE, __NV_E4M3);
    }
    __syncthreads();

    const int pr = t >> 1, half = t & 1;
    uint32_t vv[8];
#pragma unroll
    for (int j = 0; j < 8; ++j) {
        int base = pr * 65 + half * 32 + j * 4;
        vv[j] = (uint32_t)s[base] | ((uint32_t)s[base + 1] << 8) |
                ((uint32_t)s[base + 2] << 16) | ((uint32_t)s[base + 3] << 24);
    }
    uint4* dst = (uint4*)(g_x8 + ((size_t)b * HWn + hw0 + pr) * 64 + half * 32);
    dst[0] = make_uint4(vv[0], vv[1], vv[2], vv[3]);
    dst[1] = make_uint4(vv[4], vv[5], vv[6], vv[7]);
}

// ---------------- main kernel ----------------
__device__ __forceinline__ void ldsm_x4(uint32_t* r, uint32_t addr) {
    asm volatile("ldmatrix.sync.aligned.m8n8.x4.shared.b16 {%0,%1,%2,%3}, [%4];"
                 : "=r"(r[0]), "=r"(r[1]), "=r"(r[2]), "=r"(r[3]) : "r"(addr));
}
__device__ __forceinline__ void qmma(float* d, const uint32_t* a, uint32_t b0, uint32_t b1) {
    asm volatile(
        "mma.sync.aligned.m16n8k32.row.col.f32.e4m3.e4m3.f32 "
        "{%0,%1,%2,%3}, {%4,%5,%6,%7}, {%8,%9}, {%0,%1,%2,%3};"
        : "+f"(d[0]), "+f"(d[1]), "+f"(d[2]), "+f"(d[3])
        : "r"(a[0]), "r"(a[1]), "r"(a[2]), "r"(a[3]), "r"(b0), "r"(b1));
}

__global__ __launch_bounds__(256, 2)
void conv_mma(const float* __restrict__ bias, float* __restrict__ out) {
    __shared__ __align__(16) uint8_t A_s[2][4][128][16];   // [buf][ic-chunk][pix][16]
    __shared__ __align__(16) uint8_t B_s[2][4][128][16];   // [buf][ic-chunk][oc][16]
    __shared__ float bias_s[OCn];

    const int tid = threadIdx.x;
    const int wid = tid >> 5;
    const int lane = tid & 31;
    const int tile = blockIdx.x;
    const int b = blockIdx.y;

    if (tid < OCn) bias_s[tid] = bias[tid];

    const int p = tid & 127;
    const int icq = tid >> 7;
    const int pix = tile * 128 + p;
    const int h = pix / Wn;
    const int w = pix - h * Wn;

    float d[16][4];
#pragma unroll
    for (int j = 0; j < 16; ++j)
#pragma unroll
        for (int k = 0; k < 4; ++k) d[j][k] = 0.0f;

    const int m0 = wid * 16;
    // per-lane ldmatrix address components
    const int a_chunk_hi = (lane >= 16) ? 1 : 0;
    const int a_row = m0 + ((lane >> 3) & 1) * 8 + (lane & 7);
    const int b_chunk_hi = (lane >> 3) & 1;
    const int b_row_off = ((lane >= 16) ? 8 : 0) + (lane & 7);

    for (int tap = 0; tap < NTAPS; ++tap) {
        const int buf = tap & 1;
        // ---- stage A: im2col fp8, 32B per thread ----
        {
            const int gh = h + tap / 3 - 1;
            const int gw = w + tap % 3 - 1;
            uint4 v0 = make_uint4(0, 0, 0, 0), v1 = v0;
            if (gh >= 0 && gh < Hn && gw >= 0 && gw < Wn) {
                const uint4* sp = (const uint4*)(g_x8 +
                    ((size_t)b * HWn + (size_t)gh * Wn + gw) * 64 + icq * 32);
                v0 = sp[0];
                v1 = sp[1];
            }
            *(uint4*)&A_s[buf][2 * icq + 0][p][0] = v0;
            *(uint4*)&A_s[buf][2 * icq + 1][p][0] = v1;
        }
        // ---- stage B: straight 8KB copy (layout matches) ----
        {
            const uint4* wsrc = (const uint4*)(g_w8 + tap * 8192);
            uint4* wdst = (uint4*)&B_s[buf][0][0][0];
            wdst[tid] = wsrc[tid];
            wdst[tid + 256] = wsrc[tid + 256];
        }
        __syncthreads();

        // ---- compute: 2 K32 steps ----
#pragma unroll
        for (int ks = 0; ks < 2; ++ks) {
            uint32_t a[4];
            ldsm_x4(a, smem_u32(&A_s[buf][2 * ks + a_chunk_hi][a_row][0]));
#pragma unroll
            for (int half = 0; half < 2; ++half) {
                uint32_t bb[16];
#pragma unroll
                for (int j2 = 0; j2 < 4; ++j2) {
                    int jj = half * 4 + j2;   // covers n-tiles 2jj, 2jj+1
                    ldsm_x4(&bb[j2 * 4],
                            smem_u32(&B_s[buf][2 * ks + b_chunk_hi][jj * 16 + b_row_off][0]));
                }
#pragma unroll
                for (int j2 = 0; j2 < 4; ++j2) {
                    int jj = half * 4 + j2;
                    qmma(d[2 * jj + 0], a, bb[j2 * 4 + 0], bb[j2 * 4 + 1]);
                    qmma(d[2 * jj + 1], a, bb[j2 * 4 + 2], bb[j2 * 4 + 3]);
                }
            }
        }
    }

    // ---- epilogue: min over 128 OC, double tanh, store ----
    // thread holds rows {m0+q, m0+q+8} (q=lane>>2), cols {8j+2s, 8j+2s+1} (s=lane&3)
    const int s = lane & 3;
    float mlo = 1e30f, mhi = 1e30f;
#pragma unroll
    for (int j = 0; j < 16; ++j) {
        float b0 = bias_s[8 * j + 2 * s];
        float b1 = bias_s[8 * j + 2 * s + 1];
        mlo = fminf(mlo, fminf(d[j][0] + b0, d[j][1] + b1));
        mhi = fminf(mhi, fminf(d[j][2] + b0, d[j][3] + b1));
    }
    // reduce across the quad (cols)
#pragma unroll
    for (int off = 1; off <= 2; off <<= 1) {
        mlo = fminf(mlo, __shfl_xor_sync(0xffffffffu, mlo, off));
        mhi = fminf(mhi, __shfl_xor_sync(0xffffffffu, mhi, off));
    }
    if (s == 0) {
        const int q = lane >> 2;
        float* ob = out + (size_t)b * HWn + tile * 128;
        ob[m0 + q]     = tanhf(tanhf(mlo));
        ob[m0 + q + 8] = tanhf(tanhf(mhi));
    }
}

extern "C" void kernel_launch(void* const* d_in, const int* in_sizes, int n_in,
                              void* d_out, int out_size) {
    const float* x    = (const float*)d_in[0];
    const float* wgt  = (const float*)d_in[1];
    const float* bias = (const float*)d_in[2];
    float* out = (float*)d_out;

    prep_w<<<(OCn * ICn * NTAPS + 255) / 256, 256>>>(wgt);
    dim3 pgrid(NTILES, Bn);
    prep_x<<<pgrid, 256>>>(x);

    dim3 grid(NTILES, Bn);   // 392 x 16
    conv_mma<<<grid, 256>>>(bias, out);
}

// round 4
// speedup vs baseline: 6.2628x; 1.0940x over previous
#include <cuda_runtime.h>
#include <cuda_fp8.h>
#include <cstdint>
#include <math.h>

#define Bn   16
#define ICn  64
#define OCn  128
#define Hn   224
#define Wn   224
#define HWn  (Hn * Wn)
#define APIX 256                 // pixels per CTA
#define NT2  (HWn / APIX)        // 196
#define NTILES (HWn / 128)       // 392 (prep_x)
#define NTAPS 9

// fp8 scratch
__device__ uint8_t g_x8[(size_t)Bn * HWn * ICn];        // [b][hw][ic]
__device__ uint8_t g_w8[NTAPS * 4 * OCn * 16];          // [tap][chunk][oc][16]

__device__ __forceinline__ uint32_t smem_u32(const void* p) {
    uint32_t a;
    asm("{ .reg .u64 t; cvta.to.shared.u64 t, %1; cvt.u32.u64 %0, t; }"
        : "=r"(a) : "l"(p));
    return a;
}

// ---------------- prep kernels ----------------
__global__ void prep_w(const float* __restrict__ Wg) {
    int idx = blockIdx.x * 256 + threadIdx.x;
    if (idx < OCn * ICn * NTAPS) {
        int tap = idx % NTAPS;
        int ic  = (idx / NTAPS) % ICn;
        int oc  = idx / (NTAPS * ICn);
        uint8_t v = (uint8_t)__nv_cvt_float_to_fp8(Wg[idx], __NV_SATFINITE, __NV_E4M3);
        g_w8[((tap * 4 + (ic >> 4)) * OCn + oc) * 16 + (ic & 15)] = v;
    }
}

__global__ __launch_bounds__(256) void prep_x(const float* __restrict__ x) {
    __shared__ uint8_t s[128 * 65];
    const int tile = blockIdx.x, b = blockIdx.y;
    const int hw0 = tile * 128;
    const int t = threadIdx.x;
    const int ic = t >> 2, q = t & 3;

    const float4* src =
        (const float4*)(x + (size_t)b * ICn * HWn + (size_t)ic * HWn + hw0 + q * 32);
#pragma unroll
    for (int j = 0; j < 8; ++j) {
        float4 v = src[j];
        int pix = q * 32 + j * 4;
        s[(pix + 0) * 65 + ic] = (uint8_t)__nv_cvt_float_to_fp8(v.x, __NV_SATFINITE, __NV_E4M3);
        s[(pix + 1) * 65 + ic] = (uint8_t)__nv_cvt_float_to_fp8(v.y, __NV_SATFINITE, __NV_E4M3);
        s[(pix + 2) * 65 + ic] = (uint8_t)__nv_cvt_float_to_fp8(v.z, __NV_SATFINITE, __NV_E4M3);
        s[(pix + 3) * 65 + ic] = (uint8_t)__nv_cvt_float_to_fp8(v.w, __NV_SATFINITE, __NV_E4M3);
    }
    __syncthreads();

    const int pr = t >> 1, half = t & 1;
    uint32_t vv[8];
#pragma unroll
    for (int j = 0; j < 8; ++j) {
        int base = pr * 65 + half * 32 + j * 4;
        vv[j] = (uint32_t)s[base] | ((uint32_t)s[base + 1] << 8) |
                ((uint32_t)s[base + 2] << 16) | ((uint32_t)s[base + 3] << 24);
    }
    uint4* dst = (uint4*)(g_x8 + ((size_t)b * HWn + hw0 + pr) * 64 + half * 32);
    dst[0] = make_uint4(vv[0], vv[1], vv[2], vv[3]);
    dst[1] = make_uint4(vv[4], vv[5], vv[6], vv[7]);
}

// ---------------- main kernel ----------------
__device__ __forceinline__ void ldsm_x4(uint32_t* r, uint32_t addr) {
    asm volatile("ldmatrix.sync.aligned.m8n8.x4.shared.b16 {%0,%1,%2,%3}, [%4];"
                 : "=r"(r[0]), "=r"(r[1]), "=r"(r[2]), "=r"(r[3]) : "r"(addr));
}
__device__ __forceinline__ void qmma(float* d, const uint32_t* a, uint32_t b0, uint32_t b1) {
    asm volatile(
        "mma.sync.aligned.m16n8k32.row.col.f32.e4m3.e4m3.f32 "
        "{%0,%1,%2,%3}, {%4,%5,%6,%7}, {%8,%9}, {%0,%1,%2,%3};"
        : "+f"(d[0]), "+f"(d[1]), "+f"(d[2]), "+f"(d[3])
        : "r"(a[0]), "r"(a[1]), "r"(a[2]), "r"(a[3]), "r"(b0), "r"(b1));
}

// dynamic smem layout:
//   A: [2][4][APIX][16]  = 32768 B   (offset 0)
//   B: [2][4][128][16]   = 16384 B   (offset 32768)
//   bias: 128 floats     = 512 B     (offset 49152)
#define SM_A(buf, c, p)  ((uint32_t)(((buf) * 4 + (c)) * APIX + (p)) * 16)
#define SM_B(buf, c, r)  (32768u + (uint32_t)(((buf) * 4 + (c)) * 128 + (r)) * 16)
#define SM_BIAS 49152
#define SM_TOTAL 49664

__global__ __launch_bounds__(256, 1)
void conv_mma(const float* __restrict__ bias, float* __restrict__ out) {
    extern __shared__ __align__(16) uint8_t smem[];
    float* bias_s = (float*)(smem + SM_BIAS);

    const int tid = threadIdx.x;
    const int wid = tid >> 5;
    const int lane = tid & 31;
    const int tile = blockIdx.x;
    const int b = blockIdx.y;

    if (tid < OCn) bias_s[tid] = bias[tid];

    // this thread stages all 64 ic of one pixel per tap
    const int pix = tile * APIX + tid;
    const int h = pix / Wn;
    const int w = pix - h * Wn;
    const uint8_t* xb = g_x8 + (size_t)b * HWn * 64;

    float d0[16][4], d1[16][4];
#pragma unroll
    for (int j = 0; j < 16; ++j)
#pragma unroll
        for (int k = 0; k < 4; ++k) { d0[j][k] = 0.0f; d1[j][k] = 0.0f; }

    const int m0 = wid * 32;
    const int a_chunk_hi = (lane >= 16) ? 1 : 0;
    const int a_row0 = m0 + ((lane >> 3) & 1) * 8 + (lane & 7);
    const int a_row1 = a_row0 + 16;
    const int b_chunk_hi = (lane >> 3) & 1;
    const int b_row_off = ((lane >= 16) ? 8 : 0) + (lane & 7);

    uint32_t smem_base = smem_u32(smem);

    uint4 apre[4];
    uint4 bpre[2];

    // prefetch tap 0
    {
        const int gh = h - 1, gw = w - 1;
        if (gh >= 0 && gw >= 0) {
            const uint4* sp = (const uint4*)(xb + ((size_t)gh * Wn + gw) * 64);
            apre[0] = sp[0]; apre[1] = sp[1]; apre[2] = sp[2]; apre[3] = sp[3];
        } else {
            apre[0] = apre[1] = apre[2] = apre[3] = make_uint4(0, 0, 0, 0);
        }
        const uint4* wsrc = (const uint4*)(g_w8);
        bpre[0] = wsrc[tid];
        bpre[1] = wsrc[tid + 256];
    }

#pragma unroll 1
    for (int tap = 0; tap < NTAPS; ++tap) {
        const int buf = tap & 1;
        // ---- store prefetched tap into smem ----
#pragma unroll
        for (int c = 0; c < 4; ++c)
            *(uint4*)(smem + SM_A(buf, c, tid)) = apre[c];
        ((uint4*)(smem + SM_B(buf, 0, 0)))[tid] = bpre[0];
        ((uint4*)(smem + SM_B(buf, 0, 0)))[tid + 256] = bpre[1];
        __syncthreads();

        // ---- prefetch tap+1 (overlaps compute below) ----
        if (tap < NTAPS - 1) {
            const int nt = tap + 1;
            const int gh = h + nt / 3 - 1;
            const int gw = w + nt % 3 - 1;
            if (gh >= 0 && gh < Hn && gw >= 0 && gw < Wn) {
                const uint4* sp = (const uint4*)(xb + ((size_t)gh * Wn + gw) * 64);
                apre[0] = sp[0]; apre[1] = sp[1]; apre[2] = sp[2]; apre[3] = sp[3];
            } else {
                apre[0] = apre[1] = apre[2] = apre[3] = make_uint4(0, 0, 0, 0);
            }
            const uint4* wsrc = (const uint4*)(g_w8 + nt * 8192);
            bpre[0] = wsrc[tid];
            bpre[1] = wsrc[tid + 256];
        }

        // ---- compute: 2 K32 steps, two m16 A-tiles share B frags ----
#pragma unroll
        for (int ks = 0; ks < 2; ++ks) {
            uint32_t a0[4], a1[4];
            ldsm_x4(a0, smem_base + SM_A(buf, 2 * ks + a_chunk_hi, a_row0));
            ldsm_x4(a1, smem_base + SM_A(buf, 2 * ks + a_chunk_hi, a_row1));
#pragma unroll
            for (int half = 0; half < 2; ++half) {
                uint32_t bb[16];
#pragma unroll
                for (int j2 = 0; j2 < 4; ++j2) {
                    int jj = half * 4 + j2;
                    ldsm_x4(&bb[j2 * 4],
                            smem_base + SM_B(buf, 2 * ks + b_chunk_hi, jj * 16 + b_row_off));
                }
#pragma unroll
                for (int j2 = 0; j2 < 4; ++j2) {
                    int jj = half * 4 + j2;
                    qmma(d0[2 * jj + 0], a0, bb[j2 * 4 + 0], bb[j2 * 4 + 1]);
                    qmma(d0[2 * jj + 1], a0, bb[j2 * 4 + 2], bb[j2 * 4 + 3]);
                    qmma(d1[2 * jj + 0], a1, bb[j2 * 4 + 0], bb[j2 * 4 + 1]);
                    qmma(d1[2 * jj + 1], a1, bb[j2 * 4 + 2], bb[j2 * 4 + 3]);
                }
            }
        }
    }

    // ---- epilogue: min over 128 OC, double tanh, store ----
    const int s = lane & 3;
    float m00 = 1e30f, m01 = 1e30f, m10 = 1e30f, m11 = 1e30f;
#pragma unroll
    for (int j = 0; j < 16; ++j) {
        float c0 = bias_s[8 * j + 2 * s];
        float c1 = bias_s[8 * j + 2 * s + 1];
        m00 = fminf(m00, fminf(d0[j][0] + c0, d0[j][1] + c1));
        m01 = fminf(m01, fminf(d0[j][2] + c0, d0[j][3] + c1));
        m10 = fminf(m10, fminf(d1[j][0] + c0, d1[j][1] + c1));
        m11 = fminf(m11, fminf(d1[j][2] + c0, d1[j][3] + c1));
    }
#pragma unroll
    for (int off = 1; off <= 2; off <<= 1) {
        m00 = fminf(m00, __shfl_xor_sync(0xffffffffu, m00, off));
        m01 = fminf(m01, __shfl_xor_sync(0xffffffffu, m01, off));
        m10 = fminf(m10, __shfl_xor_sync(0xffffffffu, m10, off));
        m11 = fminf(m11, __shfl_xor_sync(0xffffffffu, m11, off));
    }
    if (s == 0) {
        const int q = lane >> 2;
        float* ob = out + (size_t)b * HWn + tile * APIX;
        ob[m0 + q]      = tanhf(tanhf(m00));
        ob[m0 + q + 8]  = tanhf(tanhf(m01));
        ob[m0 + q + 16] = tanhf(tanhf(m10));
        ob[m0 + q + 24] = tanhf(tanhf(m11));
    }
}

extern "C" void kernel_launch(void* const* d_in, const int* in_sizes, int n_in,
                              void* d_out, int out_size) {
    const float* x    = (const float*)d_in[0];
    const float* wgt  = (const float*)d_in[1];
    const float* bias = (const float*)d_in[2];
    float* out = (float*)d_out;

    prep_w<<<(OCn * ICn * NTAPS + 255) / 256, 256>>>(wgt);
    dim3 pgrid(NTILES, Bn);
    prep_x<<<pgrid, 256>>>(x);

    cudaFuncSetAttribute(conv_mma, cudaFuncAttributeMaxDynamicSharedMemorySize, SM_TOTAL);
    dim3 grid(NT2, Bn);   // 196 x 16
    conv_mma<<<grid, 256, SM_TOTAL>>>(bias, out);
}

// round 5
// speedup vs baseline: 7.1322x; 1.1388x over previous
#include <cuda_runtime.h>
#include <cuda_fp8.h>
#include <cuda_fp16.h>
#include <cstdint>
#include <math.h>

#define Bn   16
#define ICn  64
#define OCn  128
#define Hn   224
#define Wn   224
#define HWn  (Hn * Wn)
#define APIX 256                 // pixels per CTA
#define NT2  (HWn / APIX)        // 196
#define NTILES (HWn / 128)       // 392 (prep_x)
#define NTAPS 9

// fp8 scratch
__device__ uint8_t g_x8[(size_t)Bn * HWn * ICn];        // [b][hw][ic]
__device__ uint8_t g_w8[NTAPS * 4 * OCn * 16];          // [tap][chunk][oc][16]

__device__ __forceinline__ uint32_t smem_u32(const void* p) {
    uint32_t a;
    asm("{ .reg .u64 t; cvta.to.shared.u64 t, %1; cvt.u32.u64 %0, t; }"
        : "=r"(a) : "l"(p));
    return a;
}

// ---------------- prep kernels ----------------
__global__ void prep_w(const float* __restrict__ Wg) {
    int idx = blockIdx.x * 256 + threadIdx.x;
    if (idx < OCn * ICn * NTAPS) {
        int tap = idx % NTAPS;
        int ic  = (idx / NTAPS) % ICn;
        int oc  = idx / (NTAPS * ICn);
        uint8_t v = (uint8_t)__nv_cvt_float_to_fp8(Wg[idx], __NV_SATFINITE, __NV_E4M3);
        g_w8[((tap * 4 + (ic >> 4)) * OCn + oc) * 16 + (ic & 15)] = v;
    }
}

__global__ __launch_bounds__(256) void prep_x(const float* __restrict__ x) {
    __shared__ uint8_t s[128 * 65];
    const int tile = blockIdx.x, b = blockIdx.y;
    const int hw0 = tile * 128;
    const int t = threadIdx.x;
    const int ic = t >> 2, q = t & 3;

    const float4* src =
        (const float4*)(x + (size_t)b * ICn * HWn + (size_t)ic * HWn + hw0 + q * 32);
#pragma unroll
    for (int j = 0; j < 8; ++j) {
        float4 v = src[j];
        int pix = q * 32 + j * 4;
        s[(pix + 0) * 65 + ic] = (uint8_t)__nv_cvt_float_to_fp8(v.x, __NV_SATFINITE, __NV_E4M3);
        s[(pix + 1) * 65 + ic] = (uint8_t)__nv_cvt_float_to_fp8(v.y, __NV_SATFINITE, __NV_E4M3);
        s[(pix + 2) * 65 + ic] = (uint8_t)__nv_cvt_float_to_fp8(v.z, __NV_SATFINITE, __NV_E4M3);
        s[(pix + 3) * 65 + ic] = (uint8_t)__nv_cvt_float_to_fp8(v.w, __NV_SATFINITE, __NV_E4M3);
    }
    __syncthreads();

    const int pr = t >> 1, half = t & 1;
    uint32_t vv[8];
#pragma unroll
    for (int j = 0; j < 8; ++j) {
        int base = pr * 65 + half * 32 + j * 4;
        vv[j] = (uint32_t)s[base] | ((uint32_t)s[base + 1] << 8) |
                ((uint32_t)s[base + 2] << 16) | ((uint32_t)s[base + 3] << 24);
    }
    uint4* dst = (uint4*)(g_x8 + ((size_t)b * HWn + hw0 + pr) * 64 + half * 32);
    dst[0] = make_uint4(vv[0], vv[1], vv[2], vv[3]);
    dst[1] = make_uint4(vv[4], vv[5], vv[6], vv[7]);
}

// ---------------- main kernel ----------------
__device__ __forceinline__ void ldsm_x4(uint32_t* r, uint32_t addr) {
    asm volatile("ldmatrix.sync.aligned.m8n8.x4.shared.b16 {%0,%1,%2,%3}, [%4];"
                 : "=r"(r[0]), "=r"(r[1]), "=r"(r[2]), "=r"(r[3]) : "r"(addr));
}
// fp8 x fp8 -> fp16 accumulate (2 packed-half regs)
__device__ __forceinline__ void qmma_h(uint32_t* d, const uint32_t* a,
                                       uint32_t b0, uint32_t b1) {
    asm volatile(
        "mma.sync.aligned.m16n8k32.row.col.f16.e4m3.e4m3.f16 "
        "{%0,%1}, {%2,%3,%4,%5}, {%6,%7}, {%0,%1};"
        : "+r"(d[0]), "+r"(d[1])
        : "r"(a[0]), "r"(a[1]), "r"(a[2]), "r"(a[3]), "r"(b0), "r"(b1));
}
__device__ __forceinline__ void cp16(uint32_t dst, const void* src, uint32_t sz) {
    asm volatile("cp.async.ca.shared.global [%0], [%1], 16, %2;"
                 :: "r"(dst), "l"(src), "r"(sz) : "memory");
}
__device__ __forceinline__ void cp16g(uint32_t dst, const void* src) {
    asm volatile("cp.async.cg.shared.global [%0], [%1], 16;"
                 :: "r"(dst), "l"(src) : "memory");
}
__device__ __forceinline__ void cp_commit() {
    asm volatile("cp.async.commit_group;" ::: "memory");
}
__device__ __forceinline__ void cp_wait0() {
    asm volatile("cp.async.wait_group 0;" ::: "memory");
}

// dynamic smem layout:
//   A: [2][4][APIX][16]  = 32768 B   (offset 0)
//   B: [2][4][128][16]   = 16384 B   (offset 32768)
//   bias: 128 floats     = 512 B     (offset 49152)
#define SM_A(buf, c, p)  ((uint32_t)(((buf) * 4 + (c)) * APIX + (p)) * 16)
#define SM_B(buf, c, r)  (32768u + (uint32_t)(((buf) * 4 + (c)) * 128 + (r)) * 16)
#define SM_BIAS 49152
#define SM_TOTAL 49664

__global__ __launch_bounds__(256, 2)
void conv_mma(const float* __restrict__ bias, float* __restrict__ out) {
    extern __shared__ __align__(16) uint8_t smem[];
    float* bias_s = (float*)(smem + SM_BIAS);

    const int tid = threadIdx.x;
    const int wid = tid >> 5;
    const int lane = tid & 31;
    const int tile = blockIdx.x;
    const int b = blockIdx.y;

    if (tid < OCn) bias_s[tid] = bias[tid];

    const int pix = tile * APIX + tid;
    const int h = pix / Wn;
    const int w = pix - h * Wn;
    const uint8_t* xb = g_x8 + (size_t)b * HWn * 64;

    uint32_t d0[16][2], d1[16][2];
#pragma unroll
    for (int j = 0; j < 16; ++j) {
        d0[j][0] = d0[j][1] = 0u;
        d1[j][0] = d1[j][1] = 0u;
    }

    const int m0 = wid * 32;
    const int a_chunk_hi = (lane >= 16) ? 1 : 0;
    const int a_row0 = m0 + ((lane >> 3) & 1) * 8 + (lane & 7);
    const int a_row1 = a_row0 + 16;
    const int b_chunk_hi = (lane >> 3) & 1;
    const int b_row_off = ((lane >= 16) ? 8 : 0) + (lane & 7);

    const uint32_t smem_base = smem_u32(smem);

    // ---- issue tap 0 ----
    {
        const int gh = h - 1, gw = w - 1;
        const uint32_t sz = (gh >= 0 && gw >= 0) ? 16u : 0u;
        const uint8_t* sp = xb + ((size_t)gh * Wn + gw) * 64;
#pragma unroll
        for (int c = 0; c < 4; ++c)
            cp16(smem_base + SM_A(0, c, tid), sp + c * 16, sz);
        cp16g(smem_base + SM_B(0, 0, 0) + tid * 16, g_w8 + tid * 16);
        cp16g(smem_base + SM_B(0, 0, 0) + (tid + 256) * 16, g_w8 + (tid + 256) * 16);
        cp_commit();
    }

#pragma unroll 1
    for (int tap = 0; tap < NTAPS; ++tap) {
        const int buf = tap & 1;
        cp_wait0();
        __syncthreads();   // tap data visible to all; previous compute done

        // ---- issue tap+1 into other buffer (overlaps compute) ----
        if (tap < NTAPS - 1) {
            const int nt = tap + 1;
            const int gh = h + nt / 3 - 1;
            const int gw = w + nt % 3 - 1;
            const uint32_t sz =
                (gh >= 0 && gh < Hn && gw >= 0 && gw < Wn) ? 16u : 0u;
            const uint8_t* sp = xb + ((size_t)gh * Wn + gw) * 64;
#pragma unroll
            for (int c = 0; c < 4; ++c)
                cp16(smem_base + SM_A(buf ^ 1, c, tid), sp + c * 16, sz);
            const uint8_t* wsrc = g_w8 + nt * 8192;
            cp16g(smem_base + SM_B(buf ^ 1, 0, 0) + tid * 16, wsrc + tid * 16);
            cp16g(smem_base + SM_B(buf ^ 1, 0, 0) + (tid + 256) * 16,
                  wsrc + (tid + 256) * 16);
            cp_commit();
        }

        // ---- compute tap: 2 K32 steps, two m16 A-tiles share B frags ----
#pragma unroll
        for (int ks = 0; ks < 2; ++ks) {
            uint32_t a0[4], a1[4];
            ldsm_x4(a0, smem_base + SM_A(buf, 2 * ks + a_chunk_hi, a_row0));
            ldsm_x4(a1, smem_base + SM_A(buf, 2 * ks + a_chunk_hi, a_row1));
#pragma unroll
            for (int half = 0; half < 2; ++half) {
                uint32_t bb[16];
#pragma unroll
                for (int j2 = 0; j2 < 4; ++j2) {
                    int jj = half * 4 + j2;
                    ldsm_x4(&bb[j2 * 4],
                            smem_base + SM_B(buf, 2 * ks + b_chunk_hi, jj * 16 + b_row_off));
                }
#pragma unroll
                for (int j2 = 0; j2 < 4; ++j2) {
                    int jj = half * 4 + j2;
                    qmma_h(d0[2 * jj + 0], a0, bb[j2 * 4 + 0], bb[j2 * 4 + 1]);
                    qmma_h(d0[2 * jj + 1], a0, bb[j2 * 4 + 2], bb[j2 * 4 + 3]);
                    qmma_h(d1[2 * jj + 0], a1, bb[j2 * 4 + 0], bb[j2 * 4 + 1]);
                    qmma_h(d1[2 * jj + 1], a1, bb[j2 * 4 + 2], bb[j2 * 4 + 3]);
                }
            }
        }
    }

    // ---- epilogue: min over 128 OC, double tanh, store ----
    // d[j][0]: row (m-tile row q), cols {8j+2s, 8j+2s+1}; d[j][1]: row q+8
    const int s = lane & 3;
    float m00 = 1e30f, m01 = 1e30f, m10 = 1e30f, m11 = 1e30f;
#pragma unroll
    for (int j = 0; j < 16; ++j) {
        float c0 = bias_s[8 * j + 2 * s];
        float c1 = bias_s[8 * j + 2 * s + 1];
        float2 f;
        f = __half22float2(*(const __half2*)&d0[j][0]);
        m00 = fminf(m00, fminf(f.x + c0, f.y + c1));
        f = __half22float2(*(const __half2*)&d0[j][1]);
        m01 = fminf(m01, fminf(f.x + c0, f.y + c1));
        f = __half22float2(*(const __half2*)&d1[j][0]);
        m10 = fminf(m10, fminf(f.x + c0, f.y + c1));
        f = __half22float2(*(const __half2*)&d1[j][1]);
        m11 = fminf(m11, fminf(f.x + c0, f.y + c1));
    }
#pragma unroll
    for (int off = 1; off <= 2; off <<= 1) {
        m00 = fminf(m00, __shfl_xor_sync(0xffffffffu, m00, off));
        m01 = fminf(m01, __shfl_xor_sync(0xffffffffu, m01, off));
        m10 = fminf(m10, __shfl_xor_sync(0xffffffffu, m10, off));
        m11 = fminf(m11, __shfl_xor_sync(0xffffffffu, m11, off));
    }
    if (s == 0) {
        const int q = lane >> 2;
        float* ob = out + (size_t)b * HWn + tile * APIX;
        ob[m0 + q]      = tanhf(tanhf(m00));
        ob[m0 + q + 8]  = tanhf(tanhf(m01));
        ob[m0 + q + 16] = tanhf(tanhf(m10));
        ob[m0 + q + 24] = tanhf(tanhf(m11));
    }
}

extern "C" void kernel_launch(void* const* d_in, const int* in_sizes, int n_in,
                              void* d_out, int out_size) {
    const float* x    = (const float*)d_in[0];
    const float* wgt  = (const float*)d_in[1];
    const float* bias = (const float*)d_in[2];
    float* out = (float*)d_out;

    prep_w<<<(OCn * ICn * NTAPS + 255) / 256, 256>>>(wgt);
    dim3 pgrid(NTILES, Bn);
    prep_x<<<pgrid, 256>>>(x);

    cudaFuncSetAttribute(conv_mma, cudaFuncAttributeMaxDynamicSharedMemorySize, SM_TOTAL);
    dim3 grid(NT2, Bn);   // 196 x 16
    conv_mma<<<grid, 256, SM_TOTAL>>>(bias, out);
}